// round 1
// baseline (speedup 1.0000x reference)
#include <cuda_runtime.h>
#include <cuda_bf16.h>

// Problem constants
#define NROWS   65536      // B*T = 16*4096
#define DDIM    256
#define KCODES  1024
#define LLEV    8
#define TILE_M  64
#define THREADS 256
#define KC      128        // codes per streaming chunk
#define DCH     64         // d per streaming chunk
#define RT_STRIDE 68       // padded stride for Rt[d][r]
#define Q_STRIDE  260      // padded stride for Q[r][d]
#define ET_STRIDE 132      // padded stride for Et[d][k]

// Scratch (device globals: no allocation allowed)
__device__ double g_loss[LLEV];
__device__ float  g_norms[LLEV * KCODES];

// SMEM layout (floats):
//  Rt: DDIM*RT_STRIDE      = 17408
//  Q : TILE_M*Q_STRIDE     = 16640
//  Et: DCH*ET_STRIDE       =  8448
//  b : KCODES              =  1024
//  a : TILE_M              =    64
//  idx: TILE_M (ints)      =    64
//  red: 8 doubles          =    16 floats
#define SMEM_FLOATS (DDIM*RT_STRIDE + TILE_M*Q_STRIDE + DCH*ET_STRIDE + KCODES + TILE_M + TILE_M)
#define SMEM_BYTES  (SMEM_FLOATS*4 + 64)

__global__ void rvq_zero_kernel() {
    if (threadIdx.x < LLEV) g_loss[threadIdx.x] = 0.0;
}

// one warp per code row: ||e_k||^2
__global__ void rvq_norms_kernel(const float* __restrict__ emb) {
    int warp = (blockIdx.x * blockDim.x + threadIdx.x) >> 5;
    int lane = threadIdx.x & 31;
    if (warp >= LLEV * KCODES) return;
    const float* e = emb + (size_t)warp * DDIM;
    float s = 0.f;
    #pragma unroll
    for (int i = 0; i < DDIM / 32; ++i) {
        float v = e[lane + 32 * i];
        s = __fmaf_rn(v, v, s);
    }
    #pragma unroll
    for (int o = 16; o; o >>= 1) s += __shfl_xor_sync(0xFFFFFFFFu, s, o);
    if (lane == 0) g_norms[warp] = s;
}

__global__ void __launch_bounds__(THREADS, 1)
rvq_main_kernel(const float* __restrict__ x, const float* __restrict__ emb,
                float* __restrict__ out, long long out_size)
{
    extern __shared__ float smem[];
    float* Rt   = smem;                          // [DDIM][RT_STRIDE]  residual, transposed
    float* Q    = Rt  + DDIM * RT_STRIDE;        // [TILE_M][Q_STRIDE] quantized accumulator
    float* Et   = Q   + TILE_M * Q_STRIDE;       // [DCH][ET_STRIDE]   streamed codes, transposed
    float* b_s  = Et  + DCH * ET_STRIDE;         // [KCODES]           code norms
    float* a_s  = b_s + KCODES;                  // [TILE_M]           row norms
    int*   idx_s = (int*)(a_s + TILE_M);         // [TILE_M]
    double* red  = (double*)(idx_s + TILE_M);    // [8] per-warp loss partials (8B aligned)

    const int tid = threadIdx.x;
    const int rowbase = blockIdx.x * TILE_M;
    const int tm = tid >> 4;        // 0..15  -> rows r0..r0+3
    const int tk = tid & 15;        // 0..15  -> codes k0..k0+7
    const int r0 = tm << 2;
    const int k0 = tk << 3;

    // ---- load x tile transposed into Rt, zero Q ----
    for (int i = tid; i < TILE_M * (DDIM / 4); i += THREADS) {
        int r  = i >> 6;            // DDIM/4 = 64 vec4 per row
        int dq = i & 63;
        float4 v = *(const float4*)(x + (size_t)(rowbase + r) * DDIM + 4 * dq);
        Rt[(4 * dq + 0) * RT_STRIDE + r] = v.x;
        Rt[(4 * dq + 1) * RT_STRIDE + r] = v.y;
        Rt[(4 * dq + 2) * RT_STRIDE + r] = v.z;
        Rt[(4 * dq + 3) * RT_STRIDE + r] = v.w;
    }
    for (int i = tid; i < TILE_M * Q_STRIDE; i += THREADS) Q[i] = 0.f;

    for (int lvl = 0; lvl < LLEV; ++lvl) {
        __syncthreads();   // Rt stable (prev level's update done)

        // ---- row norms a_r = sum_d Rt[d][r]^2 ----
        {
            int r = tid >> 2, p = tid & 3;
            float s = 0.f;
            #pragma unroll 8
            for (int j = 0; j < 64; ++j) {
                float v = Rt[(p * 64 + j) * RT_STRIDE + r];
                s = __fmaf_rn(v, v, s);
            }
            s += __shfl_xor_sync(0xFFFFFFFFu, s, 1);
            s += __shfl_xor_sync(0xFFFFFFFFu, s, 2);
            if (p == 0) a_s[r] = s;
        }
        // ---- code norms into smem ----
        #pragma unroll
        for (int i = 0; i < KCODES / THREADS; ++i)
            b_s[tid + THREADS * i] = g_norms[lvl * KCODES + tid + THREADS * i];
        __syncthreads();

        float a_reg[4];
        #pragma unroll
        for (int i = 0; i < 4; ++i) a_reg[i] = a_s[r0 + i];

        float minv[4]; int mini[4];
        #pragma unroll
        for (int i = 0; i < 4; ++i) { minv[i] = 3.4028235e38f; mini[i] = 0; }

        const float* Ebase = emb + (size_t)lvl * KCODES * DDIM;

        // ---- streaming GEMM + running argmin ----
        for (int kc = 0; kc < KCODES; kc += KC) {
            float acc[4][8];
            #pragma unroll
            for (int i = 0; i < 4; ++i)
                #pragma unroll
                for (int j = 0; j < 8; ++j) acc[i][j] = 0.f;

            for (int dc = 0; dc < DDIM; dc += DCH) {
                __syncthreads();   // previous Et consumers done
                // load Et: KC codes x DCH dims, transposed
                #pragma unroll
                for (int i = 0; i < (KC * DCH / 4) / THREADS; ++i) {
                    int lin  = tid + THREADS * i;
                    int code = lin >> 4;       // 0..127
                    int dq   = lin & 15;       // 0..15 (x4 dims)
                    float4 v = *(const float4*)(Ebase + (size_t)(kc + code) * DDIM + dc + 4 * dq);
                    Et[(4 * dq + 0) * ET_STRIDE + code] = v.x;
                    Et[(4 * dq + 1) * ET_STRIDE + code] = v.y;
                    Et[(4 * dq + 2) * ET_STRIDE + code] = v.z;
                    Et[(4 * dq + 3) * ET_STRIDE + code] = v.w;
                }
                __syncthreads();

                #pragma unroll 8
                for (int dd = 0; dd < DCH; ++dd) {
                    float4 rv = *(const float4*)(Rt + (dc + dd) * RT_STRIDE + r0);
                    float4 e0 = *(const float4*)(Et + dd * ET_STRIDE + k0);
                    float4 e1 = *(const float4*)(Et + dd * ET_STRIDE + k0 + 4);
                    float rr[4] = {rv.x, rv.y, rv.z, rv.w};
                    float ee[8] = {e0.x, e0.y, e0.z, e0.w, e1.x, e1.y, e1.z, e1.w};
                    #pragma unroll
                    for (int i = 0; i < 4; ++i)
                        #pragma unroll
                        for (int j = 0; j < 8; ++j)
                            acc[i][j] = __fmaf_rn(rr[i], ee[j], acc[i][j]);
                }
            }
            // distances + running argmin (ascending k within thread -> first-min tiebreak)
            #pragma unroll
            for (int j = 0; j < 8; ++j) {
                int k = kc + k0 + j;
                float bk = b_s[k];
                #pragma unroll
                for (int i = 0; i < 4; ++i) {
                    float t    = __fadd_rn(a_reg[i], bk);
                    float dist = __fmaf_rn(-2.0f, acc[i][j], t);   // single rounding, same as fl(t-2s)
                    if (dist < minv[i]) { minv[i] = dist; mini[i] = k; }
                }
            }
        }

        // ---- cross-thread argmin reduce over the 16 tk lanes ----
        #pragma unroll
        for (int i = 0; i < 4; ++i) {
            float v = minv[i]; int ix = mini[i];
            #pragma unroll
            for (int o = 8; o; o >>= 1) {
                float ov = __shfl_xor_sync(0xFFFFFFFFu, v, o);
                int   oi = __shfl_xor_sync(0xFFFFFFFFu, ix, o);
                if (ov < v || (ov == v && oi < ix)) { v = ov; ix = oi; }
            }
            if (tk == 0) idx_s[r0 + i] = ix;
        }
        __syncthreads();

        // ---- write indices (as float, per metadata output dtype) ----
        if (tid < TILE_M) {
            long long ib = (long long)NROWS * DDIM + 1 +
                           ((long long)(rowbase + tid) * LLEV + lvl);
            if (ib < out_size) out[ib] = (float)idx_s[tid];
        }

        // ---- update phase: exact replication of reference fp32 op order ----
        double lacc = 0.0;
        #pragma unroll 4
        for (int r = 0; r < TILE_M; ++r) {
            int   code = idx_s[r];
            float q    = Ebase[(size_t)code * DDIM + tid];
            float rr   = Rt[tid * RT_STRIDE + r];
            float diff = __fsub_rn(q, rr);          // diff = quantized - residual
            float qst  = __fadd_rn(rr, diff);       // q_st = residual + diff
            lacc = __fma_rn((double)diff, (double)diff, lacc);
            Rt[tid * RT_STRIDE + r] = __fsub_rn(rr, qst);   // new residual
            Q[r * Q_STRIDE + tid] = __fadd_rn(Q[r * Q_STRIDE + tid], qst); // q_out += q_st
        }
        // ---- loss reduce (double) ----
        #pragma unroll
        for (int o = 16; o; o >>= 1) lacc += __shfl_xor_sync(0xFFFFFFFFu, lacc, o);
        if ((tid & 31) == 0) red[tid >> 5] = lacc;
        __syncthreads();
        if (tid == 0) {
            double s = 0.0;
            #pragma unroll
            for (int w = 0; w < THREADS / 32; ++w) s += red[w];
            atomicAdd(&g_loss[lvl], s);
        }
    }

    // ---- write quantized output ----
    __syncthreads();
    for (int r = 0; r < TILE_M; ++r)
        out[(size_t)(rowbase + r) * DDIM + tid] = Q[r * Q_STRIDE + tid];
}

__global__ void rvq_finalize_kernel(float* __restrict__ out, long long out_size) {
    long long ND = (long long)NROWS * DDIM;
    if (out_size <= ND) return;
    if (blockIdx.x == 0 && threadIdx.x == 0) {
        float loss = 0.f;
        for (int l = 0; l < LLEV; ++l) {
            float mean = (float)(g_loss[l] / (double)ND);       // per-level mean
            loss = __fadd_rn(loss, __fmul_rn(0.25f, mean));     // fp32 scan accumulate
        }
        out[ND] = loss;
    }
}

extern "C" void kernel_launch(void* const* d_in, const int* in_sizes, int n_in,
                              void* d_out, int out_size)
{
    const float* x   = (const float*)d_in[0];
    const float* emb = (const float*)d_in[1];
    // defensive: detect swapped input order by element counts
    if (n_in >= 2 && in_sizes[0] == LLEV * KCODES * DDIM && in_sizes[1] == NROWS * DDIM) {
        const float* t = x; x = emb; emb = t;
    }
    float* out = (float*)d_out;
    long long osz = (long long)out_size;

    rvq_zero_kernel<<<1, 32>>>();
    rvq_norms_kernel<<<(LLEV * KCODES * 32) / 256, 256>>>(emb);

    cudaFuncSetAttribute(rvq_main_kernel,
                         cudaFuncAttributeMaxDynamicSharedMemorySize, SMEM_BYTES);
    rvq_main_kernel<<<NROWS / TILE_M, THREADS, SMEM_BYTES>>>(x, emb, out, osz);

    rvq_finalize_kernel<<<1, 32>>>(out, osz);
}

// round 2
// speedup vs baseline: 1.9825x; 1.9825x over previous
#include <cuda_runtime.h>
#include <cuda_bf16.h>
#include <stdint.h>

// Problem constants
#define NROWS   65536      // B*T = 16*4096
#define DDIM    256
#define KCODES  1024
#define LLEV    8
#define TILE_M  64
#define THREADS 256
#define KC      256        // codes per chunk
#define DCH     32         // dims per staged chunk
#define RT_STRIDE 68       // padded stride for Rt[d][r]
#define Q_STRIDE  260      // padded stride for Q[r][d]

// Device-global scratch (no allocation allowed)
__device__ double g_loss[LLEV];
__device__ float  g_norms[LLEV * KCODES];
__device__ float  g_Et[LLEV * DDIM * KCODES];   // transposed codebook [l][d][k]

#define SMEM_FLOATS (DDIM*RT_STRIDE + TILE_M*Q_STRIDE + 2*DCH*KC + KCODES + TILE_M + TILE_M + 16)
#define SMEM_BYTES  (SMEM_FLOATS*4 + 64)

// ---------- small helpers ----------
__device__ __forceinline__ unsigned long long ffma2(unsigned long long a,
                                                    unsigned long long b,
                                                    unsigned long long c) {
    unsigned long long d;
    asm("fma.rn.f32x2 %0, %1, %2, %3;" : "=l"(d) : "l"(a), "l"(b), "l"(c));
    return d;
}
__device__ __forceinline__ unsigned long long pack2(float x, float y) {
    unsigned long long d;
    asm("mov.b64 %0, {%1, %2};" : "=l"(d) : "f"(x), "f"(y));
    return d;
}
__device__ __forceinline__ void unpack2(unsigned long long v, float& x, float& y) {
    asm("mov.b64 {%0, %1}, %2;" : "=f"(x), "=f"(y) : "l"(v));
}
__device__ __forceinline__ void cp_async16(void* dst_smem, const void* src) {
    unsigned d = (unsigned)__cvta_generic_to_shared(dst_smem);
    asm volatile("cp.async.cg.shared.global [%0], [%1], 16;" :: "r"(d), "l"(src) : "memory");
}
__device__ __forceinline__ void cp_commit() {
    asm volatile("cp.async.commit_group;" ::: "memory");
}
template <int N>
__device__ __forceinline__ void cp_wait() {
    asm volatile("cp.async.wait_group %0;" :: "n"(N) : "memory");
}

// ---------- tiny prep kernels ----------
__global__ void rvq_zero_kernel() {
    if (threadIdx.x < LLEV) g_loss[threadIdx.x] = 0.0;
}

// 32x32 tiled transpose: g_Et[l][d][k] = emb[l][k][d]
__global__ void rvq_transpose_kernel(const float* __restrict__ emb) {
    __shared__ float t[32][33];
    int l  = blockIdx.z;
    int k0 = blockIdx.x * 32;
    int d0 = blockIdx.y * 32;
    int tx = threadIdx.x, ty = threadIdx.y;   // 32 x 8
    #pragma unroll
    for (int i = 0; i < 32; i += 8)
        t[ty + i][tx] = emb[((size_t)l * KCODES + k0 + ty + i) * DDIM + d0 + tx];
    __syncthreads();
    #pragma unroll
    for (int i = 0; i < 32; i += 8)
        g_Et[((size_t)l * DDIM + d0 + ty + i) * KCODES + k0 + tx] = t[tx][ty + i];
}

// one warp per code row: ||e_k||^2
__global__ void rvq_norms_kernel(const float* __restrict__ emb) {
    int warp = (blockIdx.x * blockDim.x + threadIdx.x) >> 5;
    int lane = threadIdx.x & 31;
    if (warp >= LLEV * KCODES) return;
    const float* e = emb + (size_t)warp * DDIM;
    float s = 0.f;
    #pragma unroll
    for (int i = 0; i < DDIM / 32; ++i) {
        float v = e[lane + 32 * i];
        s = __fmaf_rn(v, v, s);
    }
    #pragma unroll
    for (int o = 16; o; o >>= 1) s += __shfl_xor_sync(0xFFFFFFFFu, s, o);
    if (lane == 0) g_norms[warp] = s;
}

// ---------- main fused kernel ----------
__global__ void __launch_bounds__(THREADS, 1)
rvq_main_kernel(const float* __restrict__ x, const float* __restrict__ emb,
                float* __restrict__ out, long long out_size)
{
    extern __shared__ float smem[];
    float* Rt   = smem;                          // [DDIM][RT_STRIDE]  residual, transposed
    float* Q    = Rt  + DDIM * RT_STRIDE;        // [TILE_M][Q_STRIDE] quantized accumulator
    float* Et0  = Q   + TILE_M * Q_STRIDE;       // [2][DCH][KC]       double-buffered codes
    float* b_s  = Et0 + 2 * DCH * KC;            // [KCODES]           code norms
    float* a_s  = b_s + KCODES;                  // [TILE_M]           row norms
    int*   idx_s = (int*)(a_s + TILE_M);         // [TILE_M]
    double* red  = (double*)(idx_s + TILE_M);    // per-warp loss partials

    const int tid  = threadIdx.x;
    const int warp = tid >> 5;
    const int tk   = tid & 31;          // code group 0..31 -> 4 codes each
    const int r0   = warp * 8;          // warp owns rows r0..r0+7
    const int rowbase = blockIdx.x * TILE_M;

    // ---- load x tile transposed into Rt, zero Q ----
    for (int i = tid; i < TILE_M * (DDIM / 4); i += THREADS) {
        int r  = i >> 6;
        int dq = i & 63;
        float4 v = *(const float4*)(x + (size_t)(rowbase + r) * DDIM + 4 * dq);
        Rt[(4 * dq + 0) * RT_STRIDE + r] = v.x;
        Rt[(4 * dq + 1) * RT_STRIDE + r] = v.y;
        Rt[(4 * dq + 2) * RT_STRIDE + r] = v.z;
        Rt[(4 * dq + 3) * RT_STRIDE + r] = v.w;
    }
    for (int i = tid; i < TILE_M * Q_STRIDE; i += THREADS) Q[i] = 0.f;

    for (int lvl = 0; lvl < LLEV; ++lvl) {
        __syncthreads();   // Rt stable

        // ---- row norms ----
        {
            int r = tid >> 2, p = tid & 3;
            float s = 0.f;
            #pragma unroll 8
            for (int j = 0; j < 64; ++j) {
                float v = Rt[(p * 64 + j) * RT_STRIDE + r];
                s = __fmaf_rn(v, v, s);
            }
            s += __shfl_xor_sync(0xFFFFFFFFu, s, 1);
            s += __shfl_xor_sync(0xFFFFFFFFu, s, 2);
            if (p == 0) a_s[r] = s;
        }
        // ---- code norms into smem ----
        #pragma unroll
        for (int i = 0; i < KCODES / THREADS; ++i)
            b_s[tid + THREADS * i] = g_norms[lvl * KCODES + tid + THREADS * i];
        __syncthreads();

        float a_reg[8];
        #pragma unroll
        for (int i = 0; i < 8; ++i) a_reg[i] = a_s[r0 + i];

        float minv[8]; int mini[8];
        #pragma unroll
        for (int i = 0; i < 8; ++i) { minv[i] = 3.4028235e38f; mini[i] = 0; }

        // ---- streaming GEMM over 4 chunks of 256 codes ----
        for (int kc = 0; kc < KCODES; kc += KC) {
            unsigned long long acc2[4][8];
            #pragma unroll
            for (int i = 0; i < 4; ++i)
                #pragma unroll
                for (int j = 0; j < 8; ++j) acc2[i][j] = 0ull;

            // stage(buf, dc): copy g_Et[lvl][dc..dc+31][kc..kc+255] into Et buffer
            const float* gsrc = g_Et + ((size_t)lvl * DDIM) * KCODES + kc;

            // prologue stage chunk 0 into buf 0
            {
                float* dst = Et0;
                #pragma unroll
                for (int it = 0; it < (DCH * KC / 4) / THREADS; ++it) {
                    int lin = tid + THREADS * it;
                    int dd = lin >> 6;
                    int q  = (lin & 63) << 2;
                    cp_async16(dst + dd * KC + q, gsrc + (size_t)dd * KCODES + q);
                }
                cp_commit();
            }

            int buf = 0;
            for (int dci = 0; dci < DDIM / DCH; ++dci) {
                if (dci < DDIM / DCH - 1) {
                    float* dst = Et0 + (buf ^ 1) * DCH * KC;
                    const float* s0 = gsrc + (size_t)(dci + 1) * DCH * KCODES;
                    #pragma unroll
                    for (int it = 0; it < (DCH * KC / 4) / THREADS; ++it) {
                        int lin = tid + THREADS * it;
                        int dd = lin >> 6;
                        int q  = (lin & 63) << 2;
                        cp_async16(dst + dd * KC + q, s0 + (size_t)dd * KCODES + q);
                    }
                    cp_commit();
                    cp_wait<1>();
                } else {
                    cp_wait<0>();
                }
                __syncthreads();

                const float* Eb = Et0 + buf * DCH * KC;
                const float* Rc = Rt + (size_t)(dci * DCH) * RT_STRIDE + r0;

                #pragma unroll 4
                for (int dd = 0; dd < DCH; ++dd) {
                    // rows: 4 f32x2 pairs (broadcast within warp)
                    const ulonglong2 ra = *(const ulonglong2*)(Rc + dd * RT_STRIDE);
                    const ulonglong2 rb = *(const ulonglong2*)(Rc + dd * RT_STRIDE + 4);
                    // codes: group A (tk*4..+3) and group B (128+tk*4..+3)
                    const float4 ea = *(const float4*)(Eb + dd * KC + 4 * tk);
                    const float4 eb = *(const float4*)(Eb + dd * KC + 128 + 4 * tk);
                    unsigned long long ed[8];
                    ed[0] = pack2(ea.x, ea.x); ed[1] = pack2(ea.y, ea.y);
                    ed[2] = pack2(ea.z, ea.z); ed[3] = pack2(ea.w, ea.w);
                    ed[4] = pack2(eb.x, eb.x); ed[5] = pack2(eb.y, eb.y);
                    ed[6] = pack2(eb.z, eb.z); ed[7] = pack2(eb.w, eb.w);
                    #pragma unroll
                    for (int c = 0; c < 8; ++c) {
                        acc2[0][c] = ffma2(ra.x, ed[c], acc2[0][c]);
                        acc2[1][c] = ffma2(ra.y, ed[c], acc2[1][c]);
                        acc2[2][c] = ffma2(rb.x, ed[c], acc2[2][c]);
                        acc2[3][c] = ffma2(rb.y, ed[c], acc2[3][c]);
                    }
                }
                __syncthreads();
                buf ^= 1;
            }

            // ---- distances + running argmin (ascending code order per thread) ----
            #pragma unroll
            for (int c = 0; c < 8; ++c) {
                int k = kc + ((c < 4) ? (4 * tk + c) : (128 + 4 * tk + (c - 4)));
                float bk = b_s[k];
                #pragma unroll
                for (int rp = 0; rp < 4; ++rp) {
                    float slo, shi;
                    unpack2(acc2[rp][c], slo, shi);
                    float t0 = __fadd_rn(a_reg[2 * rp],     bk);
                    float t1 = __fadd_rn(a_reg[2 * rp + 1], bk);
                    float d0 = __fmaf_rn(-2.0f, slo, t0);
                    float d1 = __fmaf_rn(-2.0f, shi, t1);
                    if (d0 < minv[2 * rp])     { minv[2 * rp]     = d0; mini[2 * rp]     = k; }
                    if (d1 < minv[2 * rp + 1]) { minv[2 * rp + 1] = d1; mini[2 * rp + 1] = k; }
                }
            }
        }

        // ---- warp argmin reduce (32 lanes share the warp's 8 rows) ----
        #pragma unroll
        for (int i = 0; i < 8; ++i) {
            float v = minv[i]; int ix = mini[i];
            #pragma unroll
            for (int o = 16; o; o >>= 1) {
                float ov = __shfl_xor_sync(0xFFFFFFFFu, v, o);
                int   oi = __shfl_xor_sync(0xFFFFFFFFu, ix, o);
                if (ov < v || (ov == v && oi < ix)) { v = ov; ix = oi; }
            }
            if (tk == 0) idx_s[r0 + i] = ix;
        }
        __syncthreads();

        // ---- write indices ----
        if (tid < TILE_M) {
            long long ib = (long long)NROWS * DDIM + 1 +
                           ((long long)(rowbase + tid) * LLEV + lvl);
            if (ib < out_size) out[ib] = (float)idx_s[tid];
        }

        // ---- update phase: exact fp32 op-order replication ----
        const float* Ebase = emb + (size_t)lvl * KCODES * DDIM;
        double lacc = 0.0;
        #pragma unroll 4
        for (int r = 0; r < TILE_M; ++r) {
            int   code = idx_s[r];
            float q    = Ebase[(size_t)code * DDIM + tid];
            float rr   = Rt[tid * RT_STRIDE + r];
            float diff = __fsub_rn(q, rr);
            float qst  = __fadd_rn(rr, diff);
            lacc = __fma_rn((double)diff, (double)diff, lacc);
            Rt[tid * RT_STRIDE + r] = __fsub_rn(rr, qst);
            Q[r * Q_STRIDE + tid] = __fadd_rn(Q[r * Q_STRIDE + tid], qst);
        }
        #pragma unroll
        for (int o = 16; o; o >>= 1) lacc += __shfl_xor_sync(0xFFFFFFFFu, lacc, o);
        if ((tid & 31) == 0) red[warp] = lacc;
        __syncthreads();
        if (tid == 0) {
            double s = 0.0;
            #pragma unroll
            for (int w = 0; w < THREADS / 32; ++w) s += red[w];
            atomicAdd(&g_loss[lvl], s);
        }
    }

    // ---- write quantized output ----
    __syncthreads();
    for (int r = 0; r < TILE_M; ++r)
        out[(size_t)(rowbase + r) * DDIM + tid] = Q[r * Q_STRIDE + tid];
}

__global__ void rvq_finalize_kernel(float* __restrict__ out, long long out_size) {
    long long ND = (long long)NROWS * DDIM;
    if (out_size <= ND) return;
    if (blockIdx.x == 0 && threadIdx.x == 0) {
        float loss = 0.f;
        for (int l = 0; l < LLEV; ++l) {
            float mean = (float)(g_loss[l] / (double)ND);
            loss = __fadd_rn(loss, __fmul_rn(0.25f, mean));
        }
        out[ND] = loss;
    }
}

extern "C" void kernel_launch(void* const* d_in, const int* in_sizes, int n_in,
                              void* d_out, int out_size)
{
    const float* x   = (const float*)d_in[0];
    const float* emb = (const float*)d_in[1];
    if (n_in >= 2 && in_sizes[0] == LLEV * KCODES * DDIM && in_sizes[1] == NROWS * DDIM) {
        const float* t = x; x = emb; emb = t;
    }
    float* out = (float*)d_out;
    long long osz = (long long)out_size;

    rvq_zero_kernel<<<1, 32>>>();
    {
        dim3 g(KCODES / 32, DDIM / 32, LLEV), b(32, 8);
        rvq_transpose_kernel<<<g, b>>>(emb);
    }
    rvq_norms_kernel<<<(LLEV * KCODES * 32) / 256, 256>>>(emb);

    cudaFuncSetAttribute(rvq_main_kernel,
                         cudaFuncAttributeMaxDynamicSharedMemorySize, SMEM_BYTES);
    rvq_main_kernel<<<NROWS / TILE_M, THREADS, SMEM_BYTES>>>(x, emb, out, osz);

    rvq_finalize_kernel<<<1, 32>>>(out, osz);
}